// round 8
// baseline (speedup 1.0000x reference)
#include <cuda_runtime.h>
#include <stdint.h>

// out[b][r] = prod_{i=0..7} v(b,i,mf[r][i]);  v = 1.0 if idx==-1 else x[b][i][idx]
// Fused single kernel. Pair tables (4 x 25 per batch), warp-autonomous:
// each warp owns a fixed 128-rule tile and builds PRIVATE tables for
// 8-batch groups in its own smem slice (single buffer; R7 showed double
// buffering doesn't help). Gathers read 25 consecutive words -> conflict-
// free; build STS addresses 100b+25p+e are a bijection mod 32 -> conflict-
// free. No block barriers.
// KEY CHANGE: 2 CTAs/SM (64 warps) via __launch_bounds__(1024,2). Register
// budget funded by packing the 16 pair-offsets as bytes in 4 uint32s
// (extracted at use) and dropping the x prefetch.

#define THREADS 1024
#define NBLK 296            // 2 CTAs per SM x 148 SMs
#define NSTREAMS 592        // NBLK*32 warps / 16 tiles

__global__ __launch_bounds__(THREADS, 2)
void fire_kernel(const float* __restrict__ x, const int* __restrict__ mf,
                 float* __restrict__ out, int n_rules, int n_groups) {
    extern __shared__ float ptab[];

    const int lane = threadIdx.x & 31;
    const int wid  = threadIdx.x >> 5;
    float* myp = ptab + wid * 800;          // 8 batches x stride 100

    const int stream = wid * NBLK + (int)blockIdx.x;   // 0..9471
    const int tile   = stream & 15;                    // 16 tiles of 128 rules
    const int g0     = stream >> 4;                    // 0..591
    const int r0     = tile << 7;

    // ---- prologue: 16 pair-offsets (each <100) packed as bytes ----
    // pk[q] holds the 4 table entries for rule r0+4*lane+q; entry for
    // table p already includes the +25*p base.
    uint32_t pk[4];
    {
        const int4* m4 = (const int4*)(mf + (size_t)(r0 + 4 * lane) * 8);
#pragma unroll
        for (int q = 0; q < 4; ++q) {
            int4 lo = m4[2 * q + 0];
            int4 hi = m4[2 * q + 1];
            uint32_t e0 = (uint32_t)((lo.x + 1) * 5 + (lo.y + 1));
            uint32_t e1 = (uint32_t)(25 + (lo.z + 1) * 5 + (lo.w + 1));
            uint32_t e2 = (uint32_t)(50 + (hi.x + 1) * 5 + (hi.y + 1));
            uint32_t e3 = (uint32_t)(75 + (hi.z + 1) * 5 + (hi.w + 1));
            pk[q] = e0 | (e1 << 8) | (e2 << 16) | (e3 << 24);
        }
    }

    // lane -> (batch slot b = lane>>2, pair p = lane&3)
    const int bslot = lane >> 2;
    const int pslot = lane & 3;
    const size_t xoff = (size_t)bslot * 32 + pslot * 8;

    for (int g = g0; g < n_groups; g += NSTREAMS) {
        // ---- build tables for this 8-batch group (conflict-free STS) ----
        {
            const float4* p4 = (const float4*)(x + (size_t)g * 256 + xoff);
            float4 xa = p4[0];
            float4 xc = p4[1];
            float Av[5] = {1.0f, xa.x, xa.y, xa.z, xa.w};
            float Cv[5] = {1.0f, xc.x, xc.y, xc.z, xc.w};
            float* dst = myp + bslot * 100 + pslot * 25;
#pragma unroll
            for (int a = 0; a < 5; ++a)
#pragma unroll
                for (int c = 0; c < 5; ++c)
                    dst[a * 5 + c] = Av[a] * Cv[c];
        }
        __syncwarp();

        // ---- compute 8 batches x 4 rules/lane ----
        float* o = out + (size_t)(g * 8) * n_rules + r0 + 4 * lane;
        const float* pb = myp;
#pragma unroll 2
        for (int b = 0; b < 8; ++b) {
            float4 v;
            v.x = (pb[pk[0] & 255u] * pb[(pk[0] >> 8) & 255u]) *
                  (pb[(pk[0] >> 16) & 255u] * pb[pk[0] >> 24]);
            v.y = (pb[pk[1] & 255u] * pb[(pk[1] >> 8) & 255u]) *
                  (pb[(pk[1] >> 16) & 255u] * pb[pk[1] >> 24]);
            v.z = (pb[pk[2] & 255u] * pb[(pk[2] >> 8) & 255u]) *
                  (pb[(pk[2] >> 16) & 255u] * pb[pk[2] >> 24]);
            v.w = (pb[pk[3] & 255u] * pb[(pk[3] >> 8) & 255u]) *
                  (pb[(pk[3] >> 16) & 255u] * pb[pk[3] >> 24]);
            *(float4*)o = v;
            pb += 100;
            o  += n_rules;
        }
        __syncwarp();   // order this iter's LDS before next iter's STS rebuild
    }
}

extern "C" void kernel_launch(void* const* d_in, const int* in_sizes, int n_in,
                              void* d_out, int out_size) {
    const float* x  = (const float*)d_in[0];
    const int*   mf = (const int*)d_in[1];
    float* out = (float*)d_out;

    const int n_rules  = in_sizes[1] / 8;     // 2048
    const int B        = in_sizes[0] / 32;    // 8192
    const int n_groups = B / 8;               // 1024

    size_t smem = 32 * 800 * sizeof(float);   // 102.4 KB per CTA, 2 CTAs/SM
    cudaFuncSetAttribute(fire_kernel, cudaFuncAttributeMaxDynamicSharedMemorySize, (int)smem);
    fire_kernel<<<NBLK, THREADS, smem>>>(x, mf, out, n_rules, n_groups);
}

// round 9
// speedup vs baseline: 1.5986x; 1.5986x over previous
#include <cuda_runtime.h>
#include <stdint.h>

// out[b][r] = prod_{i=0..7} v(b,i,mf[r][i]);  v = 1.0 if idx==-1 else x[b][i][idx]
// Fused single kernel. Pair tables (4 x 25 per batch), warp-autonomous:
// each warp owns a fixed 128-rule tile and builds PRIVATE tables for
// 8-batch groups in its own smem slice (single buffer). Gathers read 25
// consecutive words -> conflict-free; build STS addresses 100b+25p+e are
// a bijection mod 32 -> conflict-free. No block barriers.
// R8 LESSON: forcing 32 regs spills (spill traffic doubled L1 wavefronts).
// This round: 256-thread CTAs, 5 CTAs/SM (reg target 51 > ~44 live regs,
// no spill) -> 40 warps/SM for latency hiding.

#define THREADS 256
#define CTAS_PER_SM 5
#define NBLK (148 * CTAS_PER_SM)            // 740
#define NSTREAMS ((NBLK * (THREADS / 32)) / 16)   // 370

__global__ __launch_bounds__(THREADS, CTAS_PER_SM)
void fire_kernel(const float* __restrict__ x, const int* __restrict__ mf,
                 float* __restrict__ out, int n_rules, int n_groups) {
    extern __shared__ float ptab[];

    const int lane = threadIdx.x & 31;
    const int wid  = threadIdx.x >> 5;
    float* myp = ptab + wid * 800;          // 8 batches x stride 100

    const int stream = wid * NBLK + (int)blockIdx.x;   // 0..5919
    const int tile   = stream & 15;                    // 16 tiles of 128 rules
    const int g0     = stream >> 4;                    // 0..369
    const int r0     = tile << 7;

    // ---- prologue: 16 pair-offsets (each <100) packed as bytes ----
    uint32_t pk[4];
    {
        const int4* m4 = (const int4*)(mf + (size_t)(r0 + 4 * lane) * 8);
#pragma unroll
        for (int q = 0; q < 4; ++q) {
            int4 lo = m4[2 * q + 0];
            int4 hi = m4[2 * q + 1];
            uint32_t e0 = (uint32_t)((lo.x + 1) * 5 + (lo.y + 1));
            uint32_t e1 = (uint32_t)(25 + (lo.z + 1) * 5 + (lo.w + 1));
            uint32_t e2 = (uint32_t)(50 + (hi.x + 1) * 5 + (hi.y + 1));
            uint32_t e3 = (uint32_t)(75 + (hi.z + 1) * 5 + (hi.w + 1));
            pk[q] = e0 | (e1 << 8) | (e2 << 16) | (e3 << 24);
        }
    }

    // lane -> (batch slot b = lane>>2, pair p = lane&3)
    const int bslot = lane >> 2;
    const int pslot = lane & 3;
    const size_t xoff = (size_t)bslot * 32 + pslot * 8;

    for (int g = g0; g < n_groups; g += NSTREAMS) {
        // ---- build tables for this 8-batch group (conflict-free STS) ----
        {
            const float4* p4 = (const float4*)(x + (size_t)g * 256 + xoff);
            float4 xa = p4[0];
            float4 xc = p4[1];
            float Av[5] = {1.0f, xa.x, xa.y, xa.z, xa.w};
            float Cv[5] = {1.0f, xc.x, xc.y, xc.z, xc.w};
            float* dst = myp + bslot * 100 + pslot * 25;
#pragma unroll
            for (int a = 0; a < 5; ++a)
#pragma unroll
                for (int c = 0; c < 5; ++c)
                    dst[a * 5 + c] = Av[a] * Cv[c];
        }
        __syncwarp();

        // ---- compute 8 batches x 4 rules/lane ----
        float* o = out + (size_t)(g * 8) * n_rules + r0 + 4 * lane;
        const float* pb = myp;
#pragma unroll 2
        for (int b = 0; b < 8; ++b) {
            float4 v;
            v.x = (pb[pk[0] & 255u] * pb[(pk[0] >> 8) & 255u]) *
                  (pb[(pk[0] >> 16) & 255u] * pb[pk[0] >> 24]);
            v.y = (pb[pk[1] & 255u] * pb[(pk[1] >> 8) & 255u]) *
                  (pb[(pk[1] >> 16) & 255u] * pb[pk[1] >> 24]);
            v.z = (pb[pk[2] & 255u] * pb[(pk[2] >> 8) & 255u]) *
                  (pb[(pk[2] >> 16) & 255u] * pb[pk[2] >> 24]);
            v.w = (pb[pk[3] & 255u] * pb[(pk[3] >> 8) & 255u]) *
                  (pb[(pk[3] >> 16) & 255u] * pb[pk[3] >> 24]);
            *(float4*)o = v;
            pb += 100;
            o  += n_rules;
        }
        __syncwarp();   // order this iter's LDS before next iter's STS rebuild
    }
}

extern "C" void kernel_launch(void* const* d_in, const int* in_sizes, int n_in,
                              void* d_out, int out_size) {
    const float* x  = (const float*)d_in[0];
    const int*   mf = (const int*)d_in[1];
    float* out = (float*)d_out;

    const int n_rules  = in_sizes[1] / 8;     // 2048
    const int B        = in_sizes[0] / 32;    // 8192
    const int n_groups = B / 8;               // 1024

    size_t smem = (THREADS / 32) * 800 * sizeof(float);   // 25.6 KB per CTA
    cudaFuncSetAttribute(fire_kernel, cudaFuncAttributeMaxDynamicSharedMemorySize, (int)smem);
    fire_kernel<<<NBLK, THREADS, smem>>>(x, mf, out, n_rules, n_groups);
}